// round 10
// baseline (speedup 1.0000x reference)
#include <cuda_runtime.h>
#include <math.h>

#define H 256
#define TM 64
#define BK 32
#define NTHREADS 256

#define TMAX 420000
#define BMAX 8192

// ---------------- scratch (static device globals; no runtime alloc) ----------
__device__ int   d_is64;
__device__ int   d_seq32[BMAX];
__device__ int   d_rev32[TMAX];
__device__ int   d_offsets[BMAX + 1];
__device__ int   d_seg[TMAX];
__device__ float d_mean[BMAX * H];
__device__ float d_sm1[BMAX * H];
__device__ float d_posW[512 * H];     // 201 rows used
__device__ float d_alpha[TMAX];

// ---------------- helpers ----------------------------------------------------
__device__ __forceinline__ float fast_sigmoid(float x) {
    return 1.0f / (1.0f + __expf(-x));
}
__device__ __forceinline__ float fast_tanh(float x) {
    return 2.0f / (1.0f + __expf(-2.0f * x)) - 1.0f;
}

// ---------------- K0: detect int64 vs int32 for seq_len/reverse_pos ----------
__global__ void detect_kernel(const int* __restrict__ seq32view) {
    if (threadIdx.x == 0) {
        d_is64 = (seq32view[1] == 0 && seq32view[3] == 0 && seq32view[5] == 0) ? 1 : 0;
    }
}

// ---------------- K0b: convert seq_len and rev into int32 scratch ------------
__global__ void convert_kernel(const void* __restrict__ seq,
                               const void* __restrict__ rev,
                               int B, int T) {
    int is64 = d_is64;
    int stride = gridDim.x * blockDim.x;
    int i0 = blockIdx.x * blockDim.x + threadIdx.x;
    if (is64) {
        const long long* s = (const long long*)seq;
        const long long* r = (const long long*)rev;
        for (int i = i0; i < B; i += stride) d_seq32[i] = (int)s[i];
        for (int i = i0; i < T; i += stride) d_rev32[i] = (int)r[i];
    } else {
        const int* s = (const int*)seq;
        const int* r = (const int*)rev;
        for (int i = i0; i < B; i += stride) d_seq32[i] = s[i];
        for (int i = i0; i < T; i += stride) d_rev32[i] = r[i];
    }
}

// ---------------- K1: exclusive scan of seq_len -> offsets -------------------
__global__ void scan_kernel(int B) {
    __shared__ int part[1024];
    int tid = threadIdx.x;
    int chunk = (B + 1023) / 1024;
    int lo = tid * chunk;
    int hi = lo + chunk; if (hi > B) hi = B; if (lo > B) lo = B;
    int s = 0;
    for (int i = lo; i < hi; i++) s += d_seq32[i];
    part[tid] = s;
    __syncthreads();
    for (int d = 1; d < 1024; d <<= 1) {
        int v = (tid >= d) ? part[tid - d] : 0;
        __syncthreads();
        part[tid] += v;
        __syncthreads();
    }
    int base = (tid == 0) ? 0 : part[tid - 1];
    int run = base;
    for (int i = lo; i < hi; i++) { d_offsets[i] = run; run += d_seq32[i]; }
    if (tid == 1023) d_offsets[B] = part[1023];
}

// ---------------- K2: per-session mean + seg fill ----------------------------
__global__ void meanseg_kernel(const float* __restrict__ hidden) {
    int b = blockIdx.x;
    int off = d_offsets[b], end = d_offsets[b + 1];
    int len = end - off;
    int c = threadIdx.x;            // 256 threads, one per column
    float s = 0.f;
    for (int t = off; t < end; t++) s += hidden[(size_t)t * H + c];
    d_mean[(size_t)b * H + c] = s / (float)len;
    for (int t = off + c; t < end; t += H) d_seg[t] = b;
}

// ---------------- generic tiled GEMM: out = A@W + bias1 (+bias2) -------------
__launch_bounds__(NTHREADS, 2)
__global__ void gemm_bias_kernel(const float* __restrict__ A,
                                 const float* __restrict__ W,
                                 const float* __restrict__ bias1,
                                 const float* __restrict__ bias2,
                                 float* __restrict__ out, int rows) {
    extern __shared__ float smem[];
    float (*sA)[H + 8] = (float (*)[H + 8])smem;                 // 64 x 264
    float (*sW)[H]     = (float (*)[H])(smem + TM * (H + 8));    // 32 x 256

    int tid = threadIdx.x;
    int tx = tid & 15, ty = tid >> 4;
    int row0 = blockIdx.x * TM;

    for (int i = tid; i < TM * (H / 4); i += NTHREADS) {
        int r = i / (H / 4), c4 = i % (H / 4);
        float4 v = make_float4(0.f, 0.f, 0.f, 0.f);
        if (row0 + r < rows) v = ((const float4*)(A + (size_t)(row0 + r) * H))[c4];
        *(float4*)&sA[r][c4 * 4] = v;
    }

    float acc[4][16];
#pragma unroll
    for (int r = 0; r < 4; r++)
#pragma unroll
        for (int c = 0; c < 16; c++) acc[r][c] = 0.f;

    for (int kc = 0; kc < H; kc += BK) {
        __syncthreads();
        for (int i = tid; i < BK * (H / 4); i += NTHREADS) {
            int kr = i / (H / 4), c4 = i % (H / 4);
            *(float4*)&sW[kr][c4 * 4] = ((const float4*)(W + (size_t)(kc + kr) * H))[c4];
        }
        __syncthreads();
#pragma unroll
        for (int kk = 0; kk < BK; kk += 4) {
            float4 a4[4];
#pragma unroll
            for (int r = 0; r < 4; r++) a4[r] = *(const float4*)&sA[ty * 4 + r][kc + kk];
#pragma unroll
            for (int u = 0; u < 4; u++) {
                float4 b4[4];
#pragma unroll
                for (int g = 0; g < 4; g++)
                    b4[g] = *(const float4*)&sW[kk + u][4 * tx + 64 * g];
#pragma unroll
                for (int r = 0; r < 4; r++) {
                    float av = ((const float*)&a4[r])[u];
#pragma unroll
                    for (int g = 0; g < 4; g++) {
                        acc[r][g * 4 + 0] += av * b4[g].x;
                        acc[r][g * 4 + 1] += av * b4[g].y;
                        acc[r][g * 4 + 2] += av * b4[g].z;
                        acc[r][g * 4 + 3] += av * b4[g].w;
                    }
                }
            }
        }
    }

#pragma unroll
    for (int r = 0; r < 4; r++) {
        int row = row0 + ty * 4 + r;
        if (row < rows) {
#pragma unroll
            for (int g = 0; g < 4; g++)
#pragma unroll
                for (int j = 0; j < 4; j++) {
                    int c = 4 * tx + 64 * g + j;
                    float v = acc[r][g * 4 + j] + bias1[c];
                    if (bias2) v += bias2[c];
                    out[(size_t)row * H + c] = v;
                }
        }
    }
}

// ---------------- main fused kernel ------------------------------------------
__launch_bounds__(NTHREADS, 2)
__global__ void main_kernel(const float* __restrict__ hidden,
                            const float* __restrict__ WposA,
                            const float* __restrict__ W2,
                            const float* __restrict__ qw,
                            const float* __restrict__ qb,
                            int T) {
    extern __shared__ float smem[];
    float (*sA)[H + 8] = (float (*)[H + 8])smem;                  // 64 x 264
    float (*sW)[H]     = (float (*)[H])(smem + TM * (H + 8));     // 32 x 256
    float* sQw         = smem + TM * (H + 8) + BK * H;            // 256
    float (*sRed)[17]  = (float (*)[17])(sQw + H);                // 64 x 17

    int tid = threadIdx.x;
    int tx = tid & 15, ty = tid >> 4;
    int row0 = blockIdx.x * TM;

    sQw[tid] = qw[tid];

    for (int i = tid; i < TM * (H / 4); i += NTHREADS) {
        int r = i / (H / 4), c4 = i % (H / 4);
        float4 v = make_float4(0.f, 0.f, 0.f, 0.f);
        if (row0 + r < T) v = ((const float4*)(hidden + (size_t)(row0 + r) * H))[c4];
        *(float4*)&sA[r][c4 * 4] = v;
    }

    float acc[4][16];

    // ================= phase 1: hidden @ WposA =================
#pragma unroll
    for (int r = 0; r < 4; r++)
#pragma unroll
        for (int c = 0; c < 16; c++) acc[r][c] = 0.f;

    for (int kc = 0; kc < H; kc += BK) {
        __syncthreads();
        for (int i = tid; i < BK * (H / 4); i += NTHREADS) {
            int kr = i / (H / 4), c4 = i % (H / 4);
            *(float4*)&sW[kr][c4 * 4] = ((const float4*)(WposA + (size_t)(kc + kr) * H))[c4];
        }
        __syncthreads();
#pragma unroll
        for (int kk = 0; kk < BK; kk += 4) {
            float4 a4[4];
#pragma unroll
            for (int r = 0; r < 4; r++) a4[r] = *(const float4*)&sA[ty * 4 + r][kc + kk];
#pragma unroll
            for (int u = 0; u < 4; u++) {
                float4 b4[4];
#pragma unroll
                for (int g = 0; g < 4; g++)
                    b4[g] = *(const float4*)&sW[kk + u][4 * tx + 64 * g];
#pragma unroll
                for (int r = 0; r < 4; r++) {
                    float av = ((const float*)&a4[r])[u];
#pragma unroll
                    for (int g = 0; g < 4; g++) {
                        acc[r][g * 4 + 0] += av * b4[g].x;
                        acc[r][g * 4 + 1] += av * b4[g].y;
                        acc[r][g * 4 + 2] += av * b4[g].z;
                        acc[r][g * 4 + 3] += av * b4[g].w;
                    }
                }
            }
        }
    }

    // epilogue 1: tanh(acc + posW[rev[row]]), overwrite sA with PH
    __syncthreads();
#pragma unroll
    for (int r = 0; r < 4; r++) {
        int row = row0 + ty * 4 + r;
        if (row < T) {
            int p = d_rev32[row];
            const float* pw = d_posW + (size_t)p * H;
#pragma unroll
            for (int g = 0; g < 4; g++)
#pragma unroll
                for (int j = 0; j < 4; j++) {
                    int c = 4 * tx + 64 * g + j;
                    sA[ty * 4 + r][c] = fast_tanh(acc[r][g * 4 + j] + pw[c]);
                }
        } else {
#pragma unroll
            for (int g = 0; g < 4; g++)
#pragma unroll
                for (int j = 0; j < 4; j++)
                    sA[ty * 4 + r][4 * tx + 64 * g + j] = 0.f;
        }
    }

    // ================= phase 2: PH @ W2 =================
#pragma unroll
    for (int r = 0; r < 4; r++)
#pragma unroll
        for (int c = 0; c < 16; c++) acc[r][c] = 0.f;

    for (int kc = 0; kc < H; kc += BK) {
        __syncthreads();
        for (int i = tid; i < BK * (H / 4); i += NTHREADS) {
            int kr = i / (H / 4), c4 = i % (H / 4);
            *(float4*)&sW[kr][c4 * 4] = ((const float4*)(W2 + (size_t)(kc + kr) * H))[c4];
        }
        __syncthreads();
#pragma unroll
        for (int kk = 0; kk < BK; kk += 4) {
            float4 a4[4];
#pragma unroll
            for (int r = 0; r < 4; r++) a4[r] = *(const float4*)&sA[ty * 4 + r][kc + kk];
#pragma unroll
            for (int u = 0; u < 4; u++) {
                float4 b4[4];
#pragma unroll
                for (int g = 0; g < 4; g++)
                    b4[g] = *(const float4*)&sW[kk + u][4 * tx + 64 * g];
#pragma unroll
                for (int r = 0; r < 4; r++) {
                    float av = ((const float*)&a4[r])[u];
#pragma unroll
                    for (int g = 0; g < 4; g++) {
                        acc[r][g * 4 + 0] += av * b4[g].x;
                        acc[r][g * 4 + 1] += av * b4[g].y;
                        acc[r][g * 4 + 2] += av * b4[g].z;
                        acc[r][g * 4 + 3] += av * b4[g].w;
                    }
                }
            }
        }
    }

    // epilogue 2: sigmoid(acc + sm1[seg[row]]) . qw  -> alpha
    float partial[4] = {0.f, 0.f, 0.f, 0.f};
#pragma unroll
    for (int r = 0; r < 4; r++) {
        int row = row0 + ty * 4 + r;
        if (row < T) {
            int s = d_seg[row];
            const float* sm1row = d_sm1 + (size_t)s * H;
#pragma unroll
            for (int g = 0; g < 4; g++)
#pragma unroll
                for (int j = 0; j < 4; j++) {
                    int c = 4 * tx + 64 * g + j;
                    float gate = fast_sigmoid(acc[r][g * 4 + j] + sm1row[c]);
                    partial[r] += gate * sQw[c];
                }
        }
    }
    __syncthreads();
#pragma unroll
    for (int r = 0; r < 4; r++) sRed[ty * 4 + r][tx] = partial[r];
    __syncthreads();
    if (tid < TM) {
        int row = row0 + tid;
        if (row < T) {
            float s = 0.f;
#pragma unroll
            for (int i = 0; i < 16; i++) s += sRed[tid][i];
            d_alpha[row] = s + qb[0];
        }
    }
}

// ---------------- K5: per-session alpha-weighted sum -------------------------
__global__ void weighted_sum_kernel(const float* __restrict__ hidden,
                                    float* __restrict__ out) {
    int b = blockIdx.x;
    int off = d_offsets[b], end = d_offsets[b + 1];
    int c = threadIdx.x;
    float s = 0.f;
    for (int t = off; t < end; t++) s += d_alpha[t] * hidden[(size_t)t * H + c];
    out[(size_t)b * H + c] = s;
}

// ---------------- launch -----------------------------------------------------
extern "C" void kernel_launch(void* const* d_in, const int* in_sizes, int n_in,
                              void* d_out, int out_size) {
    const float* hidden    = (const float*)d_in[0];
    const float* pos_table = (const float*)d_in[1];
    const float* W_pos     = (const float*)d_in[2];
    const float* b_pos     = (const float*)d_in[3];
    const float* W1        = (const float*)d_in[4];
    const float* b1        = (const float*)d_in[5];
    const float* W2        = (const float*)d_in[6];
    const float* b2        = (const float*)d_in[7];
    const float* qw        = (const float*)d_in[8];
    const float* qb        = (const float*)d_in[9];
    const void*  seq_len   = d_in[10];
    const void*  rev       = d_in[11];

    int T = in_sizes[0] / H;        // total tokens
    int B = in_sizes[10];           // sessions
    int P = in_sizes[1] / H;        // position rows (MAX_LEN+1)

    // CRITICAL: resolve __device__ symbols to REAL device addresses.
    // Passing the symbol name directly from host code passes the host-side
    // shadow address; on GB300 (ATS/pageableMemoryAccess=1) the GPU silently
    // dereferences it as host memory (zeros) instead of faulting.
    float *p_mean = 0, *p_sm1 = 0, *p_posW = 0;
    cudaGetSymbolAddress((void**)&p_mean, d_mean);
    cudaGetSymbolAddress((void**)&p_sm1,  d_sm1);
    cudaGetSymbolAddress((void**)&p_posW, d_posW);

    const int SMEM_G = (TM * (H + 8) + BK * H) * (int)sizeof(float);
    const int SMEM_M = SMEM_G + (H + TM * 17) * (int)sizeof(float);

    cudaFuncSetAttribute(gemm_bias_kernel, cudaFuncAttributeMaxDynamicSharedMemorySize, SMEM_G);
    cudaFuncSetAttribute(main_kernel,      cudaFuncAttributeMaxDynamicSharedMemorySize, SMEM_M);

    // K0: detect int64 vs int32, convert index arrays to int32 scratch
    detect_kernel<<<1, 32>>>((const int*)seq_len);
    convert_kernel<<<256, 256>>>(seq_len, rev, B, T);
    // K1: offsets
    scan_kernel<<<1, 1024>>>(B);
    // K2: per-session mean + seg
    meanseg_kernel<<<B, NTHREADS>>>(hidden);
    // K3: sm1 = mean @ W1 + b1 + b2   (per-session)
    gemm_bias_kernel<<<(B + TM - 1) / TM, NTHREADS, SMEM_G>>>(p_mean, W1, b1, b2, p_sm1, B);
    // K4: posW = pos_table @ W_pos[256:512] + b_pos
    gemm_bias_kernel<<<(P + TM - 1) / TM, NTHREADS, SMEM_G>>>(pos_table, W_pos + H * H,
                                                              b_pos, nullptr, p_posW, P);
    // K5: fused per-token double GEMM -> alpha
    main_kernel<<<(T + TM - 1) / TM, NTHREADS, SMEM_M>>>(hidden, W_pos, W2, qw, qb, T);
    // K6: per-session weighted sum -> output
    weighted_sum_kernel<<<B, NTHREADS>>>(hidden, (float*)d_out);
}

// round 11
// speedup vs baseline: 1.8118x; 1.8118x over previous
#include <cuda_runtime.h>
#include <math.h>
#include <stdint.h>

#define H 256
#define TM 64
#define BK 32
#define NTHREADS 256

#define TMAX 420000
#define BMAX 8192

// ---------------- scratch (static device globals; no runtime alloc) ----------
__device__ int   d_is64;
__device__ int   d_seq32[BMAX];
__device__ int   d_rev32[TMAX];
__device__ int   d_offsets[BMAX + 1];
__device__ int   d_seg[TMAX];
__device__ float d_mean[BMAX * H];
__device__ float d_sm1[BMAX * H];
__device__ float d_posW[512 * H];     // 201 rows used
__device__ float d_alpha[TMAX];

// ---------------- helpers ----------------------------------------------------
__device__ __forceinline__ float fast_sigmoid(float x) {
    return 1.0f / (1.0f + __expf(-x));
}
__device__ __forceinline__ float fast_tanh(float x) {
    return 2.0f / (1.0f + __expf(-2.0f * x)) - 1.0f;
}
__device__ __forceinline__ uint32_t to_tf32(float x) {
    uint32_t u;
    asm("cvt.rna.tf32.f32 %0, %1;" : "=r"(u) : "f"(x));
    return u;
}
__device__ __forceinline__ void mma_tf32(float* c, const uint32_t* a,
                                         uint32_t b0, uint32_t b1) {
    asm volatile(
        "mma.sync.aligned.m16n8k8.row.col.f32.tf32.tf32.f32 "
        "{%0,%1,%2,%3}, {%4,%5,%6,%7}, {%8,%9}, {%0,%1,%2,%3};"
        : "+f"(c[0]), "+f"(c[1]), "+f"(c[2]), "+f"(c[3])
        : "r"(a[0]), "r"(a[1]), "r"(a[2]), "r"(a[3]), "r"(b0), "r"(b1));
}

// ---------------- K0: detect int64 vs int32 ----------------------------------
__global__ void detect_kernel(const int* __restrict__ seq32view) {
    if (threadIdx.x == 0) {
        d_is64 = (seq32view[1] == 0 && seq32view[3] == 0 && seq32view[5] == 0) ? 1 : 0;
    }
}

// ---------------- K0b: convert seq_len and rev into int32 scratch ------------
__global__ void convert_kernel(const void* __restrict__ seq,
                               const void* __restrict__ rev,
                               int B, int T) {
    int is64 = d_is64;
    int stride = gridDim.x * blockDim.x;
    int i0 = blockIdx.x * blockDim.x + threadIdx.x;
    if (is64) {
        const long long* s = (const long long*)seq;
        const long long* r = (const long long*)rev;
        for (int i = i0; i < B; i += stride) d_seq32[i] = (int)s[i];
        for (int i = i0; i < T; i += stride) d_rev32[i] = (int)r[i];
    } else {
        const int* s = (const int*)seq;
        const int* r = (const int*)rev;
        for (int i = i0; i < B; i += stride) d_seq32[i] = s[i];
        for (int i = i0; i < T; i += stride) d_rev32[i] = r[i];
    }
}

// ---------------- K1: exclusive scan of seq_len -> offsets -------------------
__global__ void scan_kernel(int B) {
    __shared__ int part[1024];
    int tid = threadIdx.x;
    int chunk = (B + 1023) / 1024;
    int lo = tid * chunk;
    int hi = lo + chunk; if (hi > B) hi = B; if (lo > B) lo = B;
    int s = 0;
    for (int i = lo; i < hi; i++) s += d_seq32[i];
    part[tid] = s;
    __syncthreads();
    for (int d = 1; d < 1024; d <<= 1) {
        int v = (tid >= d) ? part[tid - d] : 0;
        __syncthreads();
        part[tid] += v;
        __syncthreads();
    }
    int base = (tid == 0) ? 0 : part[tid - 1];
    int run = base;
    for (int i = lo; i < hi; i++) { d_offsets[i] = run; run += d_seq32[i]; }
    if (tid == 1023) d_offsets[B] = part[1023];
}

// ---------------- K2: per-session mean + seg fill ----------------------------
__global__ void meanseg_kernel(const float* __restrict__ hidden) {
    int b = blockIdx.x;
    int off = d_offsets[b], end = d_offsets[b + 1];
    int len = end - off;
    int c = threadIdx.x;
    float s = 0.f;
    for (int t = off; t < end; t++) s += hidden[(size_t)t * H + c];
    d_mean[(size_t)b * H + c] = s / (float)len;
    for (int t = off + c; t < end; t += H) d_seg[t] = b;
}

// ---------------- generic tiled GEMM (fp32): out = A@W + bias1 (+bias2) ------
__launch_bounds__(NTHREADS, 2)
__global__ void gemm_bias_kernel(const float* __restrict__ A,
                                 const float* __restrict__ W,
                                 const float* __restrict__ bias1,
                                 const float* __restrict__ bias2,
                                 float* __restrict__ out, int rows) {
    extern __shared__ float smem[];
    float (*sA)[H + 8] = (float (*)[H + 8])smem;
    float (*sW)[H]     = (float (*)[H])(smem + TM * (H + 8));

    int tid = threadIdx.x;
    int tx = tid & 15, ty = tid >> 4;
    int row0 = blockIdx.x * TM;

    for (int i = tid; i < TM * (H / 4); i += NTHREADS) {
        int r = i / (H / 4), c4 = i % (H / 4);
        float4 v = make_float4(0.f, 0.f, 0.f, 0.f);
        if (row0 + r < rows) v = ((const float4*)(A + (size_t)(row0 + r) * H))[c4];
        *(float4*)&sA[r][c4 * 4] = v;
    }

    float acc[4][16];
#pragma unroll
    for (int r = 0; r < 4; r++)
#pragma unroll
        for (int c = 0; c < 16; c++) acc[r][c] = 0.f;

    for (int kc = 0; kc < H; kc += BK) {
        __syncthreads();
        for (int i = tid; i < BK * (H / 4); i += NTHREADS) {
            int kr = i / (H / 4), c4 = i % (H / 4);
            *(float4*)&sW[kr][c4 * 4] = ((const float4*)(W + (size_t)(kc + kr) * H))[c4];
        }
        __syncthreads();
#pragma unroll
        for (int kk = 0; kk < BK; kk += 4) {
            float4 a4[4];
#pragma unroll
            for (int r = 0; r < 4; r++) a4[r] = *(const float4*)&sA[ty * 4 + r][kc + kk];
#pragma unroll
            for (int u = 0; u < 4; u++) {
                float4 b4[4];
#pragma unroll
                for (int g = 0; g < 4; g++)
                    b4[g] = *(const float4*)&sW[kk + u][4 * tx + 64 * g];
#pragma unroll
                for (int r = 0; r < 4; r++) {
                    float av = ((const float*)&a4[r])[u];
#pragma unroll
                    for (int g = 0; g < 4; g++) {
                        acc[r][g * 4 + 0] += av * b4[g].x;
                        acc[r][g * 4 + 1] += av * b4[g].y;
                        acc[r][g * 4 + 2] += av * b4[g].z;
                        acc[r][g * 4 + 3] += av * b4[g].w;
                    }
                }
            }
        }
    }

#pragma unroll
    for (int r = 0; r < 4; r++) {
        int row = row0 + ty * 4 + r;
        if (row < rows) {
#pragma unroll
            for (int g = 0; g < 4; g++)
#pragma unroll
                for (int j = 0; j < 4; j++) {
                    int c = 4 * tx + 64 * g + j;
                    float v = acc[r][g * 4 + j] + bias1[c];
                    if (bias2) v += bias2[c];
                    out[(size_t)row * H + c] = v;
                }
        }
    }
}

// ---------------- main fused TF32 tensor-core kernel -------------------------
// block: 128 token rows, 512 threads, 16 warps (4 m-groups x 4 n-groups)
// warp tile: 32 rows x 64 cols -> 2 m16 frags x 8 n8 frags, K steps of 8.
// phase 1: PH = tanh(hidden @ WposA + posW[rev])  (PH -> sA, tf32-rounded)
// phase 2: alpha = sigmoid(PH @ W2 + sm1[seg]) . qw + qb
#define TMM 128
#define SA_STRIDE 260    // 256 + 4  -> conflict-free A-fragment reads
#define SW_STRIDE 264    // 256 + 8  -> conflict-free B-fragment reads

__launch_bounds__(512, 1)
__global__ void main_tc_kernel(const float* __restrict__ hidden,
                               const float* __restrict__ WposA,
                               const float* __restrict__ W2,
                               const float* __restrict__ qw,
                               const float* __restrict__ qb,
                               int T) {
    extern __shared__ float smem[];
    float* sA     = smem;                          // 128 * 260
    float* sW     = sA + TMM * SA_STRIDE;          // 32 * 264
    float* sQw    = sW + 32 * SW_STRIDE;           // 256
    float* sAlpha = sQw + H;                       // 128

    int tid  = threadIdx.x;
    int lane = tid & 31, wid = tid >> 5;
    int warp_m = wid & 3, warp_n = wid >> 2;       // 4 x 4 warp grid
    int rm = warp_m * 32, cn = warp_n * 64;
    int gr = lane >> 2, tg = lane & 3;             // groupID, thread-in-group
    int row0 = blockIdx.x * TMM;

    if (tid < H)   sQw[tid] = qw[tid];
    if (tid < TMM) sAlpha[tid] = 0.f;

    // fill sA = tf32(hidden tile), zero-pad rows beyond T
    for (int i = tid; i < TMM * (H / 4); i += 512) {
        int r = i >> 6, c4 = i & 63;
        float4 v = make_float4(0.f, 0.f, 0.f, 0.f);
        if (row0 + r < T) v = ((const float4*)(hidden + (size_t)(row0 + r) * H))[c4];
        uint4 u;
        u.x = to_tf32(v.x); u.y = to_tf32(v.y); u.z = to_tf32(v.z); u.w = to_tf32(v.w);
        *(uint4*)&sA[r * SA_STRIDE + c4 * 4] = u;
    }
    __syncthreads();

    float acc[2][8][4];

    for (int phase = 0; phase < 2; phase++) {
        const float* Wp = (phase == 0) ? WposA : W2;

#pragma unroll
        for (int mi = 0; mi < 2; mi++)
#pragma unroll
            for (int nf = 0; nf < 8; nf++)
#pragma unroll
                for (int q = 0; q < 4; q++) acc[mi][nf][q] = 0.f;

        for (int s = 0; s < 8; s++) {
            // stage W rows [s*32, s*32+32) into sW (tf32-rounded)
            for (int i = tid; i < 32 * (H / 4); i += 512) {
                int r = i >> 6, c4 = i & 63;
                float4 v = ((const float4*)(Wp + (size_t)(s * 32 + r) * H))[c4];
                uint4 u;
                u.x = to_tf32(v.x); u.y = to_tf32(v.y); u.z = to_tf32(v.z); u.w = to_tf32(v.w);
                *(uint4*)&sW[r * SW_STRIDE + c4 * 4] = u;
            }
            __syncthreads();

#pragma unroll
            for (int j = 0; j < 4; j++) {
                int k8 = s * 32 + j * 8;      // column offset into sA
                int kl = j * 8;               // row offset into sW
                uint32_t a[2][4];
#pragma unroll
                for (int mi = 0; mi < 2; mi++) {
                    int rb = rm + mi * 16;
                    a[mi][0] = *(const uint32_t*)&sA[(rb + gr)     * SA_STRIDE + k8 + tg];
                    a[mi][1] = *(const uint32_t*)&sA[(rb + gr + 8) * SA_STRIDE + k8 + tg];
                    a[mi][2] = *(const uint32_t*)&sA[(rb + gr)     * SA_STRIDE + k8 + tg + 4];
                    a[mi][3] = *(const uint32_t*)&sA[(rb + gr + 8) * SA_STRIDE + k8 + tg + 4];
                }
#pragma unroll
                for (int nf = 0; nf < 8; nf++) {
                    int colb = cn + nf * 8 + gr;
                    uint32_t b0 = *(const uint32_t*)&sW[(kl + tg)     * SW_STRIDE + colb];
                    uint32_t b1 = *(const uint32_t*)&sW[(kl + tg + 4) * SW_STRIDE + colb];
                    mma_tf32(acc[0][nf], a[0], b0, b1);
                    mma_tf32(acc[1][nf], a[1], b0, b1);
                }
            }
            __syncthreads();
        }

        if (phase == 0) {
            // epilogue 1: PH = tanh(acc + posW[rev[row]]) -> sA (tf32)
#pragma unroll
            for (int mi = 0; mi < 2; mi++)
#pragma unroll
                for (int hi = 0; hi < 2; hi++) {
                    int rloc = rm + mi * 16 + gr + hi * 8;
                    int row = row0 + rloc;
                    const float* pw = (row < T) ? (d_posW + (size_t)d_rev32[row] * H) : 0;
#pragma unroll
                    for (int nf = 0; nf < 8; nf++)
#pragma unroll
                        for (int q = 0; q < 2; q++) {
                            int col = cn + nf * 8 + 2 * tg + q;
                            float out = 0.f;
                            if (pw) out = fast_tanh(acc[mi][nf][hi * 2 + q] + pw[col]);
                            *(uint32_t*)&sA[rloc * SA_STRIDE + col] = to_tf32(out);
                        }
                }
            __syncthreads();
        } else {
            // epilogue 2: alpha = sigmoid(acc + sm1[seg]) . qw
#pragma unroll
            for (int mi = 0; mi < 2; mi++)
#pragma unroll
                for (int hi = 0; hi < 2; hi++) {
                    int rloc = rm + mi * 16 + gr + hi * 8;
                    int row = row0 + rloc;
                    float part = 0.f;
                    if (row < T) {
                        const float* sm1r = d_sm1 + (size_t)d_seg[row] * H;
#pragma unroll
                        for (int nf = 0; nf < 8; nf++)
#pragma unroll
                            for (int q = 0; q < 2; q++) {
                                int col = cn + nf * 8 + 2 * tg + q;
                                float g = fast_sigmoid(acc[mi][nf][hi * 2 + q] + sm1r[col]);
                                part += g * sQw[col];
                            }
                    }
                    part += __shfl_xor_sync(0xffffffffu, part, 1);
                    part += __shfl_xor_sync(0xffffffffu, part, 2);
                    if (tg == 0 && row < T) atomicAdd(&sAlpha[rloc], part);
                }
            __syncthreads();
            if (tid < TMM && row0 + tid < T)
                d_alpha[row0 + tid] = sAlpha[tid] + qb[0];
        }
    }
}

// ---------------- K6: per-session alpha-weighted sum -------------------------
__global__ void weighted_sum_kernel(const float* __restrict__ hidden,
                                    float* __restrict__ out) {
    int b = blockIdx.x;
    int off = d_offsets[b], end = d_offsets[b + 1];
    int c = threadIdx.x;
    float s = 0.f;
    for (int t = off; t < end; t++) s += d_alpha[t] * hidden[(size_t)t * H + c];
    out[(size_t)b * H + c] = s;
}

// ---------------- launch -----------------------------------------------------
extern "C" void kernel_launch(void* const* d_in, const int* in_sizes, int n_in,
                              void* d_out, int out_size) {
    const float* hidden    = (const float*)d_in[0];
    const float* pos_table = (const float*)d_in[1];
    const float* W_pos     = (const float*)d_in[2];
    const float* b_pos     = (const float*)d_in[3];
    const float* W1        = (const float*)d_in[4];
    const float* b1        = (const float*)d_in[5];
    const float* W2        = (const float*)d_in[6];
    const float* b2        = (const float*)d_in[7];
    const float* qw        = (const float*)d_in[8];
    const float* qb        = (const float*)d_in[9];
    const void*  seq_len   = d_in[10];
    const void*  rev       = d_in[11];

    int T = in_sizes[0] / H;
    int B = in_sizes[10];
    int P = in_sizes[1] / H;

    // Resolve __device__ symbols to REAL device addresses (GB300 ATS trap:
    // host-shadow addresses dereference silently as host memory).
    float *p_mean = 0, *p_sm1 = 0, *p_posW = 0;
    cudaGetSymbolAddress((void**)&p_mean, d_mean);
    cudaGetSymbolAddress((void**)&p_sm1,  d_sm1);
    cudaGetSymbolAddress((void**)&p_posW, d_posW);

    const int SMEM_G = (TM * (H + 8) + BK * H) * (int)sizeof(float);
    const int SMEM_M = (TMM * SA_STRIDE + 32 * SW_STRIDE + H + TMM) * (int)sizeof(float);

    cudaFuncSetAttribute(gemm_bias_kernel, cudaFuncAttributeMaxDynamicSharedMemorySize, SMEM_G);
    cudaFuncSetAttribute(main_tc_kernel,   cudaFuncAttributeMaxDynamicSharedMemorySize, SMEM_M);

    detect_kernel<<<1, 32>>>((const int*)seq_len);
    convert_kernel<<<256, 256>>>(seq_len, rev, B, T);
    scan_kernel<<<1, 1024>>>(B);
    meanseg_kernel<<<B, NTHREADS>>>(hidden);
    // sm1 = mean @ W1 + b1 + b2   (per-session, fp32 exact)
    gemm_bias_kernel<<<(B + TM - 1) / TM, NTHREADS, SMEM_G>>>(p_mean, W1, b1, b2, p_sm1, B);
    // posW = pos_table @ W_pos[256:512] + b_pos   (fp32 exact)
    gemm_bias_kernel<<<(P + TM - 1) / TM, NTHREADS, SMEM_G>>>(pos_table, W_pos + H * H,
                                                              b_pos, nullptr, p_posW, P);
    // fused per-token double GEMM (tf32 tensor cores) -> alpha
    main_tc_kernel<<<(T + TMM - 1) / TMM, 512, SMEM_M>>>(hidden, W_pos, W2, qw, qb, T);
    // per-session weighted sum -> output
    weighted_sum_kernel<<<B, NTHREADS>>>(hidden, (float*)d_out);
}

// round 15
// speedup vs baseline: 2.0183x; 1.1140x over previous
#include <cuda_runtime.h>
#include <math.h>
#include <stdint.h>

#define H 256
#define TM 64
#define BK 32
#define NTHREADS 256

#define TMAX 420000
#define BMAX 8192

extern __shared__ char smem[];   // single dynamic-smem declaration for all kernels

// ---------------- scratch (static device globals; no runtime alloc) ----------
__device__ int   d_is64;
__device__ int   d_seq32[BMAX];
__device__ int   d_rev32[TMAX];
__device__ int   d_offsets[BMAX + 1];
__device__ int   d_seg[TMAX];
__device__ float d_mean[BMAX * H];
__device__ float d_sm1[BMAX * H];
__device__ float d_posW[512 * H];      // 201 rows used
__device__ float d_alpha[TMAX];
__device__ float d_Wr1[H * H];         // W_pos top half [k][n], tf32-rounded
__device__ float d_Wr2[H * H];         // W2 [k][n], tf32-rounded

// ---------------- helpers ----------------------------------------------------
__device__ __forceinline__ float fast_sigmoid(float x) {
    return 1.0f / (1.0f + __expf(-x));
}
__device__ __forceinline__ float fast_tanh(float x) {
    return 2.0f / (1.0f + __expf(-2.0f * x)) - 1.0f;
}
__device__ __forceinline__ uint32_t to_tf32(float x) {
    uint32_t u;
    asm("cvt.rna.tf32.f32 %0, %1;" : "=r"(u) : "f"(x));
    return u;
}
__device__ __forceinline__ uint32_t smem_u32(const void* p) {
    uint32_t a;
    asm("{ .reg .u64 t; cvta.to.shared.u64 t, %1; cvt.u32.u64 %0, t; }" : "=r"(a) : "l"(p));
    return a;
}
__device__ __forceinline__ void mma_tf32(float* c, const uint32_t* a,
                                         uint32_t b0, uint32_t b1) {
    asm volatile(
        "mma.sync.aligned.m16n8k8.row.col.f32.tf32.tf32.f32 "
        "{%0,%1,%2,%3}, {%4,%5,%6,%7}, {%8,%9}, {%0,%1,%2,%3};"
        : "+f"(c[0]), "+f"(c[1]), "+f"(c[2]), "+f"(c[3])
        : "r"(a[0]), "r"(a[1]), "r"(a[2]), "r"(a[3]), "r"(b0), "r"(b1));
}
__device__ __forceinline__ void cp_async16(uint32_t dst, const void* src) {
    asm volatile("cp.async.ca.shared.global [%0], [%1], 16;" :: "r"(dst), "l"(src));
}
#define CP_COMMIT() asm volatile("cp.async.commit_group;" ::: "memory")
#define CP_WAIT1()  asm volatile("cp.async.wait_group 1;" ::: "memory")

// ---------------- K0: detect int64 vs int32 ----------------------------------
__global__ void detect_kernel(const int* __restrict__ seq32view) {
    if (threadIdx.x == 0) {
        d_is64 = (seq32view[1] == 0 && seq32view[3] == 0 && seq32view[5] == 0) ? 1 : 0;
    }
}

// ---------------- K0b: convert seq_len and rev into int32 scratch ------------
__global__ void convert_kernel(const void* __restrict__ seq,
                               const void* __restrict__ rev,
                               int B, int T) {
    int is64 = d_is64;
    int stride = gridDim.x * blockDim.x;
    int i0 = blockIdx.x * blockDim.x + threadIdx.x;
    if (is64) {
        const long long* s = (const long long*)seq;
        const long long* r = (const long long*)rev;
        for (int i = i0; i < B; i += stride) d_seq32[i] = (int)s[i];
        for (int i = i0; i < T; i += stride) d_rev32[i] = (int)r[i];
    } else {
        const int* s = (const int*)seq;
        const int* r = (const int*)rev;
        for (int i = i0; i < B; i += stride) d_seq32[i] = s[i];
        for (int i = i0; i < T; i += stride) d_rev32[i] = r[i];
    }
}

// ---------------- K0c: tf32-round weights (same [k][n] layout) ---------------
__global__ void round_kernel(const float* __restrict__ W, float* __restrict__ out) {
    int i = blockIdx.x * 256 + threadIdx.x;
    out[i] = __uint_as_float(to_tf32(W[i]));
}

// ---------------- K1: exclusive scan of seq_len -> offsets -------------------
__global__ void scan_kernel(int B) {
    __shared__ int part[1024];
    int tid = threadIdx.x;
    int chunk = (B + 1023) / 1024;
    int lo = tid * chunk;
    int hi = lo + chunk; if (hi > B) hi = B; if (lo > B) lo = B;
    int s = 0;
    for (int i = lo; i < hi; i++) s += d_seq32[i];
    part[tid] = s;
    __syncthreads();
    for (int d = 1; d < 1024; d <<= 1) {
        int v = (tid >= d) ? part[tid - d] : 0;
        __syncthreads();
        part[tid] += v;
        __syncthreads();
    }
    int base = (tid == 0) ? 0 : part[tid - 1];
    int run = base;
    for (int i = lo; i < hi; i++) { d_offsets[i] = run; run += d_seq32[i]; }
    if (tid == 1023) d_offsets[B] = part[1023];
}

// ---------------- K2: per-session mean + seg fill ----------------------------
__global__ void meanseg_kernel(const float* __restrict__ hidden) {
    int b = blockIdx.x;
    int off = d_offsets[b], end = d_offsets[b + 1];
    int len = end - off;
    int c = threadIdx.x;
    float s = 0.f;
    for (int t = off; t < end; t++) s += hidden[(size_t)t * H + c];
    d_mean[(size_t)b * H + c] = s / (float)len;
    for (int t = off + c; t < end; t += H) d_seg[t] = b;
}

// ---------------- generic tiled GEMM (fp32): out = A@W + bias1 (+bias2) ------
__launch_bounds__(NTHREADS, 2)
__global__ void gemm_bias_kernel(const float* __restrict__ A,
                                 const float* __restrict__ W,
                                 const float* __restrict__ bias1,
                                 const float* __restrict__ bias2,
                                 float* __restrict__ out, int rows) {
    float* smf = (float*)smem;
    float (*sA)[H + 8] = (float (*)[H + 8])smf;
    float (*sW)[H]     = (float (*)[H])(smf + TM * (H + 8));

    int tid = threadIdx.x;
    int tx = tid & 15, ty = tid >> 4;
    int row0 = blockIdx.x * TM;

    for (int i = tid; i < TM * (H / 4); i += NTHREADS) {
        int r = i / (H / 4), c4 = i % (H / 4);
        float4 v = make_float4(0.f, 0.f, 0.f, 0.f);
        if (row0 + r < rows) v = ((const float4*)(A + (size_t)(row0 + r) * H))[c4];
        *(float4*)&sA[r][c4 * 4] = v;
    }

    float acc[4][16];
#pragma unroll
    for (int r = 0; r < 4; r++)
#pragma unroll
        for (int c = 0; c < 16; c++) acc[r][c] = 0.f;

    for (int kc = 0; kc < H; kc += BK) {
        __syncthreads();
        for (int i = tid; i < BK * (H / 4); i += NTHREADS) {
            int kr = i / (H / 4), c4 = i % (H / 4);
            *(float4*)&sW[kr][c4 * 4] = ((const float4*)(W + (size_t)(kc + kr) * H))[c4];
        }
        __syncthreads();
#pragma unroll
        for (int kk = 0; kk < BK; kk += 4) {
            float4 a4[4];
#pragma unroll
            for (int r = 0; r < 4; r++) a4[r] = *(const float4*)&sA[ty * 4 + r][kc + kk];
#pragma unroll
            for (int u = 0; u < 4; u++) {
                float4 b4[4];
#pragma unroll
                for (int g = 0; g < 4; g++)
                    b4[g] = *(const float4*)&sW[kk + u][4 * tx + 64 * g];
#pragma unroll
                for (int r = 0; r < 4; r++) {
                    float av = ((const float*)&a4[r])[u];
#pragma unroll
                    for (int g = 0; g < 4; g++) {
                        acc[r][g * 4 + 0] += av * b4[g].x;
                        acc[r][g * 4 + 1] += av * b4[g].y;
                        acc[r][g * 4 + 2] += av * b4[g].z;
                        acc[r][g * 4 + 3] += av * b4[g].w;
                    }
                }
            }
        }
    }

#pragma unroll
    for (int r = 0; r < 4; r++) {
        int row = row0 + ty * 4 + r;
        if (row < rows) {
#pragma unroll
            for (int g = 0; g < 4; g++)
#pragma unroll
                for (int j = 0; j < 4; j++) {
                    int c = 4 * tx + 64 * g + j;
                    float v = acc[r][g * 4 + j] + bias1[c];
                    if (bias2) v += bias2[c];
                    out[(size_t)row * H + c] = v;
                }
        }
    }
}

// ---------------- main fused TF32 tensor-core kernel (cp.async pipelined) ----
// block: 128 token rows, 512 threads, 16 warps (4 m x 4 n), warp tile 32x64.
// 16 global stages of 32 K-rows: stages 0..7 = phase 1 (WposA), 8..15 = phase 2 (W2).
// W double-buffered via cp.async; stage g+2 issued right after compute of g.
#define TMM 128
#define SA_STRIDE 260    // 256 + 4  -> conflict-free A-fragment reads
#define SW_STRIDE 264    // 256 + 8  -> conflict-free B-fragment reads

__launch_bounds__(512, 1)
__global__ void main_tc_kernel(const float* __restrict__ hidden,
                               const float* __restrict__ qw,
                               const float* __restrict__ qb,
                               int T) {
    float* smf    = (float*)smem;
    float* sA     = smf;                           // 128 * 260
    float* sW     = sA + TMM * SA_STRIDE;          // 2 * 32 * 264
    float* sQw    = sW + 2 * 32 * SW_STRIDE;       // 256
    float* sAlpha = sQw + H;                       // 128
    uint32_t sW_base = smem_u32(sW);

    int tid  = threadIdx.x;
    int lane = tid & 31, wid = tid >> 5;
    int warp_m = wid & 3, warp_n = wid >> 2;       // 4 x 4 warp grid
    int rm = warp_m * 32, cn = warp_n * 64;
    int gr = lane >> 2, tg = lane & 3;             // groupID, thread-in-group
    int row0 = blockIdx.x * TMM;

    if (tid < H)   sQw[tid] = qw[tid];
    if (tid < TMM) sAlpha[tid] = 0.f;

    // fill sA = tf32(hidden tile), zero-pad rows beyond T
    for (int i = tid; i < TMM * (H / 4); i += 512) {
        int r = i >> 6, c4 = i & 63;
        float4 v = make_float4(0.f, 0.f, 0.f, 0.f);
        if (row0 + r < T) v = ((const float4*)(hidden + (size_t)(row0 + r) * H))[c4];
        uint4 u;
        u.x = to_tf32(v.x); u.y = to_tf32(v.y); u.z = to_tf32(v.z); u.w = to_tf32(v.w);
        *(uint4*)&sA[r * SA_STRIDE + c4 * 4] = u;
    }

    // ---- cp.async stage issue: 32 W rows (8 KB) into buffer g&1 ----
    auto issue_stage = [&](int g) {
        if (g < 16) {
            const float* src = ((g < 8) ? d_Wr1 : d_Wr2) + (size_t)(g & 7) * 32 * H;
#pragma unroll
            for (int it = 0; it < 4; it++) {
                int i = tid + it * 512;            // 2048 chunks of 16B
                int r = i >> 6, c = i & 63;
                uint32_t dst = sW_base + (uint32_t)(((g & 1) * 32 + r) * SW_STRIDE + c * 4) * 4u;
                cp_async16(dst, src + (size_t)r * H + c * 4);
            }
        }
        CP_COMMIT();                               // empty group ok past the end
    };

    issue_stage(0);
    issue_stage(1);

    float acc[2][8][4];
#pragma unroll
    for (int mi = 0; mi < 2; mi++)
#pragma unroll
        for (int nf = 0; nf < 8; nf++)
#pragma unroll
            for (int q = 0; q < 4; q++) acc[mi][nf][q] = 0.f;

    __syncthreads();   // sA ready (also pre-stage issue done by all threads)

    for (int g = 0; g < 16; g++) {
        CP_WAIT1();                                // stage g landed (per-thread)
        __syncthreads();                           // all threads' copies visible
        const float* buf = sW + (g & 1) * 32 * SW_STRIDE;
        int kc = (g & 7) * 32;

#pragma unroll
        for (int j = 0; j < 4; j++) {
            int k8 = kc + j * 8;                   // column offset into sA
            int kl = j * 8;                        // row offset into buf
            uint32_t a[2][4];
#pragma unroll
            for (int mi = 0; mi < 2; mi++) {
                int rb = rm + mi * 16;
                a[mi][0] = *(const uint32_t*)&sA[(rb + gr)     * SA_STRIDE + k8 + tg];
                a[mi][1] = *(const uint32_t*)&sA[(rb + gr + 8) * SA_STRIDE + k8 + tg];
                a[mi][2] = *(const uint32_t*)&sA[(rb + gr)     * SA_STRIDE + k8 + tg + 4];
                a[mi][3] = *(const uint32_t*)&sA[(rb + gr + 8) * SA_STRIDE + k8 + tg + 4];
            }
#pragma unroll
            for (int nf = 0; nf < 8; nf++) {
                int colb = cn + nf * 8 + gr;
                uint32_t b0 = *(const uint32_t*)&buf[(kl + tg)     * SW_STRIDE + colb];
                uint32_t b1 = *(const uint32_t*)&buf[(kl + tg + 4) * SW_STRIDE + colb];
                mma_tf32(acc[0][nf], a[0], b0, b1);
                mma_tf32(acc[1][nf], a[1], b0, b1);
            }
        }
        __syncthreads();                           // done reading buf g&1
        issue_stage(g + 2);                        // overwrite it for stage g+2

        if (g == 7) {
            // ---- epilogue 1: PH = tanh(acc + posW[rev[row]]) -> sA (tf32) ----
#pragma unroll
            for (int mi = 0; mi < 2; mi++)
#pragma unroll
                for (int hi = 0; hi < 2; hi++) {
                    int rloc = rm + mi * 16 + gr + hi * 8;
                    int row = row0 + rloc;
                    const float* pw = (row < T) ? (d_posW + (size_t)d_rev32[row] * H) : 0;
#pragma unroll
                    for (int nf = 0; nf < 8; nf++)
#pragma unroll
                        for (int q = 0; q < 2; q++) {
                            int col = cn + nf * 8 + 2 * tg + q;
                            float out = 0.f;
                            if (pw) out = fast_tanh(acc[mi][nf][hi * 2 + q] + pw[col]);
                            *(uint32_t*)&sA[rloc * SA_STRIDE + col] = to_tf32(out);
                        }
                }
#pragma unroll
            for (int mi = 0; mi < 2; mi++)
#pragma unroll
                for (int nf = 0; nf < 8; nf++)
#pragma unroll
                    for (int q = 0; q < 4; q++) acc[mi][nf][q] = 0.f;
            __syncthreads();                       // PH visible to all warps
        }
    }

    // ---- epilogue 2: alpha = sigmoid(acc + sm1[seg]) . qw ----
#pragma unroll
    for (int mi = 0; mi < 2; mi++)
#pragma unroll
        for (int hi = 0; hi < 2; hi++) {
            int rloc = rm + mi * 16 + gr + hi * 8;
            int row = row0 + rloc;
            float part = 0.f;
            if (row < T) {
                const float* sm1r = d_sm1 + (size_t)d_seg[row] * H;
#pragma unroll
                for (int nf = 0; nf < 8; nf++)
#pragma unroll
                    for (int q = 0; q < 2; q++) {
                        int col = cn + nf * 8 + 2 * tg + q;
                        float g = fast_sigmoid(acc[mi][nf][hi * 2 + q] + sm1r[col]);
                        part += g * sQw[col];
                    }
            }
            part += __shfl_xor_sync(0xffffffffu, part, 1);
            part += __shfl_xor_sync(0xffffffffu, part, 2);
            if (tg == 0 && row < T) atomicAdd(&sAlpha[rloc], part);
        }
    __syncthreads();
    if (tid < TMM && row0 + tid < T)
        d_alpha[row0 + tid] = sAlpha[tid] + qb[0];
}

// ---------------- K6: per-session alpha-weighted sum -------------------------
__global__ void weighted_sum_kernel(const float* __restrict__ hidden,
                                    float* __restrict__ out) {
    int b = blockIdx.x;
    int off = d_offsets[b], end = d_offsets[b + 1];
    int c = threadIdx.x;
    float s = 0.f;
    for (int t = off; t < end; t++) s += d_alpha[t] * hidden[(size_t)t * H + c];
    out[(size_t)b * H + c] = s;
}

// ---------------- launch -----------------------------------------------------
extern "C" void kernel_launch(void* const* d_in, const int* in_sizes, int n_in,
                              void* d_out, int out_size) {
    const float* hidden    = (const float*)d_in[0];
    const float* pos_table = (const float*)d_in[1];
    const float* W_pos     = (const float*)d_in[2];
    const float* b_pos     = (const float*)d_in[3];
    const float* W1        = (const float*)d_in[4];
    const float* b1        = (const float*)d_in[5];
    const float* W2        = (const float*)d_in[6];
    const float* b2        = (const float*)d_in[7];
    const float* qw        = (const float*)d_in[8];
    const float* qb        = (const float*)d_in[9];
    const void*  seq_len   = d_in[10];
    const void*  rev       = d_in[11];

    int T = in_sizes[0] / H;
    int B = in_sizes[10];
    int P = in_sizes[1] / H;

    // Resolve __device__ symbols to REAL device addresses (GB300 ATS trap:
    // host-shadow addresses dereference silently as host memory).
    float *p_mean = 0, *p_sm1 = 0, *p_posW = 0, *p_Wr1 = 0, *p_Wr2 = 0;
    cudaGetSymbolAddress((void**)&p_mean, d_mean);
    cudaGetSymbolAddress((void**)&p_sm1,  d_sm1);
    cudaGetSymbolAddress((void**)&p_posW, d_posW);
    cudaGetSymbolAddress((void**)&p_Wr1,  d_Wr1);
    cudaGetSymbolAddress((void**)&p_Wr2,  d_Wr2);

    const int SMEM_G = (TM * (H + 8) + BK * H) * (int)sizeof(float);
    const int SMEM_M = (TMM * SA_STRIDE + 2 * 32 * SW_STRIDE + H + TMM) * (int)sizeof(float);

    cudaFuncSetAttribute(gemm_bias_kernel, cudaFuncAttributeMaxDynamicSharedMemorySize, SMEM_G);
    cudaFuncSetAttribute(main_tc_kernel,   cudaFuncAttributeMaxDynamicSharedMemorySize, SMEM_M);

    detect_kernel<<<1, 32>>>((const int*)seq_len);
    convert_kernel<<<256, 256>>>(seq_len, rev, B, T);
    round_kernel<<<H * H / 256, 256>>>(W_pos, p_Wr1);    // W_pos rows 0..255
    round_kernel<<<H * H / 256, 256>>>(W2, p_Wr2);
    scan_kernel<<<1, 1024>>>(B);
    meanseg_kernel<<<B, NTHREADS>>>(hidden);
    // sm1 = mean @ W1 + b1 + b2   (per-session, fp32 exact)
    gemm_bias_kernel<<<(B + TM - 1) / TM, NTHREADS, SMEM_G>>>(p_mean, W1, b1, b2, p_sm1, B);
    // posW = pos_table @ W_pos[256:512] + b_pos   (fp32 exact)
    gemm_bias_kernel<<<(P + TM - 1) / TM, NTHREADS, SMEM_G>>>(pos_table, W_pos + H * H,
                                                              b_pos, nullptr, p_posW, P);
    // fused per-token double GEMM (tf32 mma.sync, cp.async pipelined) -> alpha
    main_tc_kernel<<<(T + TMM - 1) / TMM, 512, SMEM_M>>>(hidden, qw, qb, T);
    // per-session weighted sum -> output
    weighted_sum_kernel<<<B, NTHREADS>>>(hidden, (float*)d_out);
}

// round 17
// speedup vs baseline: 2.2174x; 1.0987x over previous
#include <cuda_runtime.h>
#include <math.h>
#include <stdint.h>

#define H 256
#define TM 64
#define BK 32
#define NTHREADS 256

#define TMAX 420000
#define BMAX 8192

extern __shared__ char smem[];   // single dynamic-smem declaration for all kernels

// ---------------- scratch (static device globals; no runtime alloc) ----------
__device__ int   d_seq32[BMAX];
__device__ int   d_rev32[TMAX];
__device__ int   d_offsets[BMAX + 1];
__device__ int   d_seg[TMAX];
__device__ float d_mean[BMAX * H];
__device__ float d_sm1[BMAX * H];
__device__ float d_posW[512 * H];      // 201 rows used
__device__ float d_alpha[TMAX];
__device__ float d_Wr1[H * H];         // W_pos top half [k][n], tf32-rounded
__device__ float d_Wr2[H * H];         // W2 [k][n], tf32-rounded

// ---------------- helpers ----------------------------------------------------
__device__ __forceinline__ float fast_sigmoid(float x) {
    return 1.0f / (1.0f + __expf(-x));
}
__device__ __forceinline__ float fast_tanh(float x) {
    return 2.0f / (1.0f + __expf(-2.0f * x)) - 1.0f;
}
__device__ __forceinline__ uint32_t to_tf32(float x) {
    uint32_t u;
    asm("cvt.rna.tf32.f32 %0, %1;" : "=r"(u) : "f"(x));
    return u;
}
__device__ __forceinline__ uint32_t smem_u32(const void* p) {
    uint32_t a;
    asm("{ .reg .u64 t; cvta.to.shared.u64 t, %1; cvt.u32.u64 %0, t; }" : "=r"(a) : "l"(p));
    return a;
}
__device__ __forceinline__ void mma_tf32(float* c, const uint32_t* a,
                                         uint32_t b0, uint32_t b1) {
    asm volatile(
        "mma.sync.aligned.m16n8k8.row.col.f32.tf32.tf32.f32 "
        "{%0,%1,%2,%3}, {%4,%5,%6,%7}, {%8,%9}, {%0,%1,%2,%3};"
        : "+f"(c[0]), "+f"(c[1]), "+f"(c[2]), "+f"(c[3])
        : "r"(a[0]), "r"(a[1]), "r"(a[2]), "r"(a[3]), "r"(b0), "r"(b1));
}
__device__ __forceinline__ void cp_async16(uint32_t dst, const void* src) {
    asm volatile("cp.async.ca.shared.global [%0], [%1], 16;" :: "r"(dst), "l"(src));
}
#define CP_COMMIT() asm volatile("cp.async.commit_group;" ::: "memory")
#define CP_WAIT1()  asm volatile("cp.async.wait_group 1;" ::: "memory")

// ---------------- K1: convert seq_len and rev into int32 scratch -------------
// int64 detection inlined: seq values >= 10, so genuine-int32 odd slots != 0;
// int64-viewed-as-int32 has high words (odd slots) == 0.
__global__ void convert_kernel(const void* __restrict__ seq,
                               const void* __restrict__ rev,
                               int B, int T) {
    const int* sv = (const int*)seq;
    int is64 = (sv[1] == 0 && sv[3] == 0 && sv[5] == 0) ? 1 : 0;
    int stride = gridDim.x * blockDim.x;
    int i0 = blockIdx.x * blockDim.x + threadIdx.x;
    if (is64) {
        const long long* s = (const long long*)seq;
        const long long* r = (const long long*)rev;
        for (int i = i0; i < B; i += stride) d_seq32[i] = (int)s[i];
        for (int i = i0; i < T; i += stride) d_rev32[i] = (int)r[i];
    } else {
        const int* s = (const int*)seq;
        const int* r = (const int*)rev;
        for (int i = i0; i < B; i += stride) d_seq32[i] = s[i];
        for (int i = i0; i < T; i += stride) d_rev32[i] = r[i];
    }
}

// ---------------- K2: exclusive scan of seq_len -> offsets -------------------
__global__ void scan_kernel(int B) {
    __shared__ int part[1024];
    int tid = threadIdx.x;
    int chunk = (B + 1023) / 1024;
    int lo = tid * chunk;
    int hi = lo + chunk; if (hi > B) hi = B; if (lo > B) lo = B;
    int s = 0;
    for (int i = lo; i < hi; i++) s += d_seq32[i];
    part[tid] = s;
    __syncthreads();
    for (int d = 1; d < 1024; d <<= 1) {
        int v = (tid >= d) ? part[tid - d] : 0;
        __syncthreads();
        part[tid] += v;
        __syncthreads();
    }
    int base = (tid == 0) ? 0 : part[tid - 1];
    int run = base;
    for (int i = lo; i < hi; i++) { d_offsets[i] = run; run += d_seq32[i]; }
    if (tid == 1023) d_offsets[B] = part[1023];
}

// ---------------- K3: tf32-round both weight matrices (fused) ----------------
__global__ void round_kernel(const float* __restrict__ Wa, const float* __restrict__ Wb) {
    int i = blockIdx.x * 256 + threadIdx.x;
    if (i < H * H) d_Wr1[i] = __uint_as_float(to_tf32(Wa[i]));
    else           d_Wr2[i - H * H] = __uint_as_float(to_tf32(Wb[i - H * H]));
}

// ---------------- K4: per-session mean + seg fill ----------------------------
__global__ void meanseg_kernel(const float* __restrict__ hidden) {
    int b = blockIdx.x;
    int off = d_offsets[b], end = d_offsets[b + 1];
    int len = end - off;
    int c = threadIdx.x;
    float s = 0.f;
    for (int t = off; t < end; t++) s += hidden[(size_t)t * H + c];
    d_mean[(size_t)b * H + c] = s / (float)len;
    for (int t = off + c; t < end; t += H) d_seg[t] = b;
}

// ---------------- K5: fused fp32 GEMMs: sm1 (blocks<nb1) + posW --------------
__launch_bounds__(NTHREADS, 2)
__global__ void gemm_comb_kernel(const float* __restrict__ A1, const float* __restrict__ Wm1,
                                 const float* __restrict__ b1a, const float* __restrict__ b1b,
                                 float* __restrict__ out1, int rows1,
                                 const float* __restrict__ A2, const float* __restrict__ Wm2,
                                 const float* __restrict__ b2a,
                                 float* __restrict__ out2, int rows2) {
    int nb1 = (rows1 + TM - 1) / TM;
    const float* A; const float* W; const float* bias1; const float* bias2;
    float* out; int rows; int row0;
    if ((int)blockIdx.x < nb1) {
        A = A1; W = Wm1; bias1 = b1a; bias2 = b1b; out = out1; rows = rows1;
        row0 = blockIdx.x * TM;
    } else {
        A = A2; W = Wm2; bias1 = b2a; bias2 = 0; out = out2; rows = rows2;
        row0 = (blockIdx.x - nb1) * TM;
    }

    float* smf = (float*)smem;
    float (*sA)[H + 8] = (float (*)[H + 8])smf;
    float (*sW)[H]     = (float (*)[H])(smf + TM * (H + 8));

    int tid = threadIdx.x;
    int tx = tid & 15, ty = tid >> 4;

    for (int i = tid; i < TM * (H / 4); i += NTHREADS) {
        int r = i / (H / 4), c4 = i % (H / 4);
        float4 v = make_float4(0.f, 0.f, 0.f, 0.f);
        if (row0 + r < rows) v = ((const float4*)(A + (size_t)(row0 + r) * H))[c4];
        *(float4*)&sA[r][c4 * 4] = v;
    }

    float acc[4][16];
#pragma unroll
    for (int r = 0; r < 4; r++)
#pragma unroll
        for (int c = 0; c < 16; c++) acc[r][c] = 0.f;

    for (int kc = 0; kc < H; kc += BK) {
        __syncthreads();
        for (int i = tid; i < BK * (H / 4); i += NTHREADS) {
            int kr = i / (H / 4), c4 = i % (H / 4);
            *(float4*)&sW[kr][c4 * 4] = ((const float4*)(W + (size_t)(kc + kr) * H))[c4];
        }
        __syncthreads();
#pragma unroll
        for (int kk = 0; kk < BK; kk += 4) {
            float4 a4[4];
#pragma unroll
            for (int r = 0; r < 4; r++) a4[r] = *(const float4*)&sA[ty * 4 + r][kc + kk];
#pragma unroll
            for (int u = 0; u < 4; u++) {
                float4 b4[4];
#pragma unroll
                for (int g = 0; g < 4; g++)
                    b4[g] = *(const float4*)&sW[kk + u][4 * tx + 64 * g];
#pragma unroll
                for (int r = 0; r < 4; r++) {
                    float av = ((const float*)&a4[r])[u];
#pragma unroll
                    for (int g = 0; g < 4; g++) {
                        acc[r][g * 4 + 0] += av * b4[g].x;
                        acc[r][g * 4 + 1] += av * b4[g].y;
                        acc[r][g * 4 + 2] += av * b4[g].z;
                        acc[r][g * 4 + 3] += av * b4[g].w;
                    }
                }
            }
        }
    }

#pragma unroll
    for (int r = 0; r < 4; r++) {
        int row = row0 + ty * 4 + r;
        if (row < rows) {
#pragma unroll
            for (int g = 0; g < 4; g++)
#pragma unroll
                for (int j = 0; j < 4; j++) {
                    int c = 4 * tx + 64 * g + j;
                    float v = acc[r][g * 4 + j] + bias1[c];
                    if (bias2) v += bias2[c];
                    out[(size_t)row * H + c] = v;
                }
        }
    }
}

// ---------------- K6 (main): fused TF32 mma.sync, 2 CTAs/SM ------------------
// block: 64 token rows, 256 threads, 8 warps (2 m x 4 n), warp tile 32x64.
// 32 global stages of 16 K-rows: stages 0..15 = phase 1 (WposA), 16..31 = W2.
// W double-buffered via cp.async; stage g+2 issued right after compute of g.
#define TMM 64
#define SA_STRIDE 260    // 256 + 4  -> conflict-free A-fragment reads
#define SW_STRIDE 264    // 256 + 8  -> conflict-free B-fragment reads
#define STG_ROWS 16

__launch_bounds__(256, 2)
__global__ void main_tc_kernel(const float* __restrict__ hidden,
                               const float* __restrict__ qw,
                               const float* __restrict__ qb,
                               int T) {
    float* smf    = (float*)smem;
    float* sA     = smf;                           // 64 * 260
    float* sW     = sA + TMM * SA_STRIDE;          // 2 * 16 * 264
    float* sQw    = sW + 2 * STG_ROWS * SW_STRIDE; // 256
    float* sAlpha = sQw + H;                       // 64
    uint32_t sW_base = smem_u32(sW);

    int tid  = threadIdx.x;
    int lane = tid & 31, wid = tid >> 5;
    int warp_m = wid & 1, warp_n = wid >> 1;       // 2 x 4 warp grid
    int rm = warp_m * 32, cn = warp_n * 64;
    int gr = lane >> 2, tg = lane & 3;             // groupID, thread-in-group
    int row0 = blockIdx.x * TMM;

    if (tid < H)   sQw[tid] = qw[tid];
    if (tid < TMM) sAlpha[tid] = 0.f;

    // fill sA = tf32(hidden tile), zero-pad rows beyond T
    for (int i = tid; i < TMM * (H / 4); i += 256) {
        int r = i >> 6, c4 = i & 63;
        float4 v = make_float4(0.f, 0.f, 0.f, 0.f);
        if (row0 + r < T) v = ((const float4*)(hidden + (size_t)(row0 + r) * H))[c4];
        uint4 u;
        u.x = to_tf32(v.x); u.y = to_tf32(v.y); u.z = to_tf32(v.z); u.w = to_tf32(v.w);
        *(uint4*)&sA[r * SA_STRIDE + c4 * 4] = u;
    }

    // ---- cp.async stage issue: 16 W rows (4 KB) into buffer g&1 ----
    auto issue_stage = [&](int g) {
        if (g < 32) {
            const float* src = ((g < 16) ? d_Wr1 : d_Wr2) + (size_t)(g & 15) * STG_ROWS * H;
#pragma unroll
            for (int it = 0; it < 4; it++) {
                int i = tid + it * 256;            // 1024 chunks of 16B
                int r = i >> 6, c = i & 63;
                uint32_t dst = sW_base + (uint32_t)(((g & 1) * STG_ROWS + r) * SW_STRIDE + c * 4) * 4u;
                cp_async16(dst, src + (size_t)r * H + c * 4);
            }
        }
        CP_COMMIT();                               // empty group ok past the end
    };

    issue_stage(0);
    issue_stage(1);

    float acc[2][8][4];
#pragma unroll
    for (int mi = 0; mi < 2; mi++)
#pragma unroll
        for (int nf = 0; nf < 8; nf++)
#pragma unroll
            for (int q = 0; q < 4; q++) acc[mi][nf][q] = 0.f;

    __syncthreads();   // sA ready

    for (int g = 0; g < 32; g++) {
        CP_WAIT1();                                // stage g landed (per-thread)
        __syncthreads();                           // all threads' copies visible
        const float* buf = sW + (g & 1) * STG_ROWS * SW_STRIDE;
        int kc = (g & 15) * STG_ROWS;

#pragma unroll
        for (int j = 0; j < 2; j++) {
            int k8 = kc + j * 8;                   // column offset into sA
            int kl = j * 8;                        // row offset into buf
            uint32_t a[2][4];
#pragma unroll
            for (int mi = 0; mi < 2; mi++) {
                int rb = rm + mi * 16;
                a[mi][0] = *(const uint32_t*)&sA[(rb + gr)     * SA_STRIDE + k8 + tg];
                a[mi][1] = *(const uint32_t*)&sA[(rb + gr + 8) * SA_STRIDE + k8 + tg];
                a[mi][2] = *(const uint32_t*)&sA[(rb + gr)     * SA_STRIDE + k8 + tg + 4];
                a[mi][3] = *(const uint32_t*)&sA[(rb + gr + 8) * SA_STRIDE + k8 + tg + 4];
            }
#pragma unroll
            for (int nf = 0; nf < 8; nf++) {
                int colb = cn + nf * 8 + gr;
                uint32_t b0 = *(const uint32_t*)&buf[(kl + tg)     * SW_STRIDE + colb];
                uint32_t b1 = *(const uint32_t*)&buf[(kl + tg + 4) * SW_STRIDE + colb];
                mma_tf32(acc[0][nf], a[0], b0, b1);
                mma_tf32(acc[1][nf], a[1], b0, b1);
            }
        }
        __syncthreads();                           // done reading buf g&1
        issue_stage(g + 2);                        // overwrite it for stage g+2

        if (g == 15) {
            // ---- epilogue 1: PH = tanh(acc + posW[rev[row]]) -> sA (tf32) ----
#pragma unroll
            for (int mi = 0; mi < 2; mi++)
#pragma unroll
                for (int hi = 0; hi < 2; hi++) {
                    int rloc = rm + mi * 16 + gr + hi * 8;
                    int row = row0 + rloc;
                    const float* pw = (row < T) ? (d_posW + (size_t)d_rev32[row] * H) : 0;
#pragma unroll
                    for (int nf = 0; nf < 8; nf++)
#pragma unroll
                        for (int q = 0; q < 2; q++) {
                            int col = cn + nf * 8 + 2 * tg + q;
                            float out = 0.f;
                            if (pw) out = fast_tanh(acc[mi][nf][hi * 2 + q] + pw[col]);
                            *(uint32_t*)&sA[rloc * SA_STRIDE + col] = to_tf32(out);
                        }
                }
#pragma unroll
            for (int mi = 0; mi < 2; mi++)
#pragma unroll
                for (int nf = 0; nf < 8; nf++)
#pragma unroll
                    for (int q = 0; q < 4; q++) acc[mi][nf][q] = 0.f;
            __syncthreads();                       // PH visible to all warps
        }
    }

    // ---- epilogue 2: alpha = sigmoid(acc + sm1[seg]) . qw ----
#pragma unroll
    for (int mi = 0; mi < 2; mi++)
#pragma unroll
        for (int hi = 0; hi < 2; hi++) {
            int rloc = rm + mi * 16 + gr + hi * 8;
            int row = row0 + rloc;
            float part = 0.f;
            if (row < T) {
                const float* sm1r = d_sm1 + (size_t)d_seg[row] * H;
#pragma unroll
                for (int nf = 0; nf < 8; nf++)
#pragma unroll
                    for (int q = 0; q < 2; q++) {
                        int col = cn + nf * 8 + 2 * tg + q;
                        float g = fast_sigmoid(acc[mi][nf][hi * 2 + q] + sm1r[col]);
                        part += g * sQw[col];
                    }
            }
            part += __shfl_xor_sync(0xffffffffu, part, 1);
            part += __shfl_xor_sync(0xffffffffu, part, 2);
            if (tg == 0 && row < T) atomicAdd(&sAlpha[rloc], part);
        }
    __syncthreads();
    if (tid < TMM && row0 + tid < T)
        d_alpha[row0 + tid] = sAlpha[tid] + qb[0];
}

// ---------------- K7: per-session alpha-weighted sum -------------------------
__global__ void weighted_sum_kernel(const float* __restrict__ hidden,
                                    float* __restrict__ out) {
    int b = blockIdx.x;
    int off = d_offsets[b], end = d_offsets[b + 1];
    int c = threadIdx.x;
    float s = 0.f;
    for (int t = off; t < end; t++) s += d_alpha[t] * hidden[(size_t)t * H + c];
    out[(size_t)b * H + c] = s;
}

// ---------------- launch -----------------------------------------------------
extern "C" void kernel_launch(void* const* d_in, const int* in_sizes, int n_in,
                              void* d_out, int out_size) {
    const float* hidden    = (const float*)d_in[0];
    const float* pos_table = (const float*)d_in[1];
    const float* W_pos     = (const float*)d_in[2];
    const float* b_pos     = (const float*)d_in[3];
    const float* W1        = (const float*)d_in[4];
    const float* b1        = (const float*)d_in[5];
    const float* W2        = (const float*)d_in[6];
    const float* b2        = (const float*)d_in[7];
    const float* qw        = (const float*)d_in[8];
    const float* qb        = (const float*)d_in[9];
    const void*  seq_len   = d_in[10];
    const void*  rev       = d_in[11];

    int T = in_sizes[0] / H;
    int B = in_sizes[10];
    int P = in_sizes[1] / H;

    // Resolve __device__ symbols to REAL device addresses (GB300 ATS trap:
    // host-shadow addresses dereference silently as host memory).
    float *p_mean = 0, *p_sm1 = 0, *p_posW = 0;
    cudaGetSymbolAddress((void**)&p_mean, d_mean);
    cudaGetSymbolAddress((void**)&p_sm1,  d_sm1);
    cudaGetSymbolAddress((void**)&p_posW, d_posW);

    const int SMEM_G = (TM * (H + 8) + BK * H) * (int)sizeof(float);
    const int SMEM_M = (TMM * SA_STRIDE + 2 * STG_ROWS * SW_STRIDE + H + TMM) * (int)sizeof(float);

    cudaFuncSetAttribute(gemm_comb_kernel, cudaFuncAttributeMaxDynamicSharedMemorySize, SMEM_G);
    cudaFuncSetAttribute(main_tc_kernel,   cudaFuncAttributeMaxDynamicSharedMemorySize, SMEM_M);

    int nb1 = (B + TM - 1) / TM, nb2 = (P + TM - 1) / TM;

    // Launch order matters for ncu (-s 5 -c 1): main_tc_kernel must be launch #6.
    convert_kernel<<<256, 256>>>(seq_len, rev, B, T);                          // 1
    scan_kernel<<<1, 1024>>>(B);                                               // 2
    round_kernel<<<2 * H * H / 256, 256>>>(W_pos, W2);                         // 3
    meanseg_kernel<<<B, NTHREADS>>>(hidden);                                   // 4
    gemm_comb_kernel<<<nb1 + nb2, NTHREADS, SMEM_G>>>(p_mean, W1, b1, b2,      // 5
                                                      p_sm1, B,
                                                      pos_table, W_pos + H * H, b_pos,
                                                      p_posW, P);
    main_tc_kernel<<<(T + TMM - 1) / TMM, 256, SMEM_M>>>(hidden, qw, qb, T);   // 6
    weighted_sum_kernel<<<B, NTHREADS>>>(hidden, (float*)d_out);               // 7
}